// round 10
// baseline (speedup 1.0000x reference)
#include <cuda_runtime.h>
#include <cstdint>

#define TOK 4096
#define HID 1024
#define KVW 256
#define SEQ 2048

// scratch
__device__ float g_q [TOK * HID];
__device__ float g_k [TOK * KVW];
__device__ float g_v [TOK * KVW];
__device__ float g_x [TOK * HID];
__device__ float g_t1[TOK * HID];
__device__ float g_o [TOK * HID];
__device__ float g_f1[TOK * HID];

__device__ __forceinline__ unsigned su32(const void* p) {
    return (unsigned)__cvta_generic_to_shared(p);
}
__device__ __forceinline__ void cp16(unsigned s, const void* g) {
    asm volatile("cp.async.cg.shared.global [%0], [%1], 16;" :: "r"(s), "l"(g));
}
__device__ __forceinline__ void cp_commit() { asm volatile("cp.async.commit_group;"); }
template<int N> __device__ __forceinline__ void cp_wait() {
    asm volatile("cp.async.wait_group %0;" :: "n"(N));
}

__device__ __forceinline__ void mma_tf32(float c[4],
                                         unsigned a0, unsigned a1, unsigned a2, unsigned a3,
                                         unsigned b0, unsigned b1) {
    asm volatile(
        "mma.sync.aligned.m16n8k8.row.col.f32.tf32.tf32.f32 "
        "{%0,%1,%2,%3}, {%4,%5,%6,%7}, {%8,%9}, {%0,%1,%2,%3};"
        : "+f"(c[0]), "+f"(c[1]), "+f"(c[2]), "+f"(c[3])
        : "r"(a0), "r"(a1), "r"(a2), "r"(a3), "r"(b0), "r"(b1));
}

// ldmatrix x4: four 8x(16B) matrices; lane 8i+j supplies row j of matrix i.
__device__ __forceinline__ void ldsm_x4(unsigned r[4], unsigned addr) {
    asm volatile("ldmatrix.sync.aligned.m8n8.x4.shared.b16 {%0,%1,%2,%3}, [%4];"
                 : "=r"(r[0]), "=r"(r[1]), "=r"(r[2]), "=r"(r[3]) : "r"(addr));
}

// ================= GEMM: 128x128 block, 4 warps x (64x64) warp tiles, BK=16 ============
// (round-8 proven configuration)
template<int MODE>
__device__ __forceinline__ void gemm_body(
    const float* __restrict__ A, const float* __restrict__ Wb,
    const float* __restrict__ biasl, const float* __restrict__ res,
    float* __restrict__ C, int N, int ncol0, int K, int bm)
{
    __shared__ float As[2][128 * 20];
    __shared__ float Ws[2][128 * 20];

    const int tid = threadIdx.x, lane = tid & 31, w = tid >> 5;
    const int wm = w & 1, wn = w >> 1;
    const int qr = lane >> 2, qc = lane & 3;

    const int arow = lane & 15;
    const int acol = (lane >> 4) << 2;
    const int brow = ((lane >> 4) << 3) + (lane & 7);
    const int bcol = ((lane >> 3) & 1) << 2;

    const float* Ab = A + (size_t)bm * 128 * K;

    float acc[4][8][4] = {};
    const int NK = K / 16;

    const int sr = tid >> 2;
    const int sc4 = (tid & 3) * 4;

    auto stage = [&](int kt, int bf) {
        #pragma unroll
        for (int i = 0; i < 4; i++) {
            int r = i * 32 + sr;
            cp16(su32(&As[bf][r * 20 + sc4]), Ab + (size_t)r * K + kt * 16 + sc4);
            cp16(su32(&Ws[bf][r * 20 + sc4]), Wb + (size_t)r * K + kt * 16 + sc4);
        }
    };

    stage(0, 0);
    cp_commit();

    for (int kt = 0; kt < NK; kt++) {
        const int buf = kt & 1;
        if (kt + 1 < NK) {
            stage(kt + 1, buf ^ 1);
            cp_commit();
            cp_wait<1>();
        } else {
            cp_wait<0>();
        }
        __syncthreads();

        const float* as = As[buf];
        const float* ws = Ws[buf];
        #pragma unroll
        for (int ks = 0; ks < 2; ks++) {
            unsigned a[4][4], bf_[8][2];
            #pragma unroll
            for (int mt = 0; mt < 4; mt++)
                ldsm_x4(a[mt], su32(&as[(wm * 64 + mt * 16 + arow) * 20 + ks * 8 + acol]));
            #pragma unroll
            for (int p = 0; p < 4; p++) {
                unsigned t[4];
                ldsm_x4(t, su32(&ws[(wn * 64 + p * 16 + brow) * 20 + ks * 8 + bcol]));
                bf_[2 * p][0] = t[0]; bf_[2 * p][1] = t[1];
                bf_[2 * p + 1][0] = t[2]; bf_[2 * p + 1][1] = t[3];
            }
            #pragma unroll
            for (int mt = 0; mt < 4; mt++)
                #pragma unroll
                for (int nt = 0; nt < 8; nt++)
                    mma_tf32(acc[mt][nt], a[mt][0], a[mt][1], a[mt][2], a[mt][3],
                             bf_[nt][0], bf_[nt][1]);
        }
        __syncthreads();
    }

    #pragma unroll
    for (int mt = 0; mt < 4; mt++) {
        #pragma unroll
        for (int nt = 0; nt < 8; nt++) {
            int lcol = wn * 64 + nt * 8 + qc * 2;
            int col  = ncol0 + lcol;
            float b0 = biasl[lcol], b1 = biasl[lcol + 1];
            #pragma unroll
            for (int half = 0; half < 2; half++) {
                int row = bm * 128 + wm * 64 + mt * 16 + qr + half * 8;
                float v0 = acc[mt][nt][half * 2 + 0] + b0;
                float v1 = acc[mt][nt][half * 2 + 1] + b1;
                if (MODE == 1) {
                    v0 += res[(size_t)row * N + col];
                    v1 += res[(size_t)row * N + col + 1];
                }
                if (MODE == 2) { v0 = fmaxf(v0, 0.f); v1 = fmaxf(v1, 0.f); }
                float2 o; o.x = v0; o.y = v1;
                *(float2*)&C[(size_t)row * N + col] = o;
            }
        }
    }
}

template<int MODE>
__global__ __launch_bounds__(128)
void gemm128(const float* __restrict__ A, const float* __restrict__ W,
             const float* __restrict__ bias, const float* __restrict__ res,
             float* __restrict__ C, int N, int K) {
    int bn = blockIdx.x;
    gemm_body<MODE>(A, W + (size_t)bn * 128 * K, bias + bn * 128, res, C,
                    N, bn * 128, K, blockIdx.y);
}

__global__ __launch_bounds__(128)
void qkv_gemm(const float* __restrict__ hidden,
              const float* __restrict__ wq, const float* __restrict__ bq,
              const float* __restrict__ wk, const float* __restrict__ bk,
              const float* __restrict__ wv, const float* __restrict__ bv,
              float* __restrict__ q, float* __restrict__ k, float* __restrict__ v) {
    int bn = blockIdx.x;
    const float* W; const float* bias; float* C; int N, nc;
    if (bn < 8)       { int j = bn;      W = wq + (size_t)j * 128 * HID; bias = bq + j * 128; C = q; N = HID; nc = j * 128; }
    else if (bn < 10) { int j = bn - 8;  W = wk + (size_t)j * 128 * HID; bias = bk + j * 128; C = k; N = KVW; nc = j * 128; }
    else              { int j = bn - 10; W = wv + (size_t)j * 128 * HID; bias = bv + j * 128; C = v; N = KVW; nc = j * 128; }
    gemm_body<0>(hidden, W, bias, nullptr, C, N, nc, HID, blockIdx.y);
}

// ================= flash attention: V transposed in smem, all fragments via ldmatrix ====
#define KPAD 68
#define VTP  36
__global__ __launch_bounds__(256)
void flash5(const float* __restrict__ q, const float* __restrict__ kk,
            const float* __restrict__ vv, float* __restrict__ X) {
    __shared__ float Ks[2][32 * KPAD];
    __shared__ float Vt[2][64 * VTP];    // Vt[d][key]

    const int b = blockIdx.z, h = blockIdx.y, qt = blockIdx.x, g = h >> 2;
    const int tid = threadIdx.x, lane = tid & 31, w = tid >> 5;
    const int qr = lane >> 2, qc = lane & 3;

    // ldmatrix coords (shared by K and Vt fragment loads)
    const int brow = ((lane >> 4) << 3) + (lane & 7);
    const int bcol = ((lane >> 3) & 1) << 2;

    unsigned qa[2][8][4];
    #pragma unroll
    for (int mt = 0; mt < 2; mt++) {
        const float* qb = q + (size_t)(b * SEQ + qt * 256 + w * 32 + mt * 16) * HID + h * 64;
        #pragma unroll
        for (int ks = 0; ks < 8; ks++) {
            qa[mt][ks][0] = __float_as_uint(qb[(size_t)qr       * HID + ks * 8 + qc]     * 0.125f);
            qa[mt][ks][1] = __float_as_uint(qb[(size_t)(qr + 8) * HID + ks * 8 + qc]     * 0.125f);
            qa[mt][ks][2] = __float_as_uint(qb[(size_t)qr       * HID + ks * 8 + qc + 4] * 0.125f);
            qa[mt][ks][3] = __float_as_uint(qb[(size_t)(qr + 8) * HID + ks * 8 + qc + 4] * 0.125f);
        }
    }

    float l[2][2] = {};
    float O[2][8][4] = {};

    const float* kb = kk + (size_t)b * SEQ * KVW + g * 64;
    const float* vb = vv + (size_t)b * SEQ * KVW + g * 64;

    // K staging (cp.async): thread covers 2x16B of the 32x64 K tile
    const int r = tid >> 3;
    const int c4 = (tid & 7) * 8;
    auto stageK = [&](int kt, int bf) {
        const float* krow = kb + (size_t)(kt * 32 + r) * KVW + c4;
        cp16(su32(&Ks[bf][r * KPAD + c4]),     krow);
        cp16(su32(&Ks[bf][r * KPAD + c4 + 4]), krow + 4);
    };

    // V transpose staging: warp w covers dims w*8..w*8+7, lane = key
    const float* vlane = vb + (size_t)lane * KVW + w * 8;   // + kt*32*KVW per tile
    float4 va, vb4;
    auto ldgV = [&](int kt) {
        const float* p = vlane + (size_t)kt * 32 * KVW;
        va  = *(const float4*)p;
        vb4 = *(const float4*)(p + 4);
    };
    auto stsV = [&](int bf) {
        float* vt = Vt[bf];
        vt[(w * 8 + 0) * VTP + lane] = va.x;
        vt[(w * 8 + 1) * VTP + lane] = va.y;
        vt[(w * 8 + 2) * VTP + lane] = va.z;
        vt[(w * 8 + 3) * VTP + lane] = va.w;
        vt[(w * 8 + 4) * VTP + lane] = vb4.x;
        vt[(w * 8 + 5) * VTP + lane] = vb4.y;
        vt[(w * 8 + 6) * VTP + lane] = vb4.z;
        vt[(w * 8 + 7) * VTP + lane] = vb4.w;
    };

    // prologue: tile 0
    ldgV(0);
    stsV(0);
    stageK(0, 0);
    cp_commit();

    const int NT = SEQ / 32;
    for (int kt = 0; kt < NT; kt++) {
        const int buf = kt & 1;
        __syncthreads();                 // all warps done reading buf^1 (iter kt-1)
        if (kt + 1 < NT) {
            ldgV(kt + 1);                // LDG in flight across this tile's compute
            stageK(kt + 1, buf ^ 1);
            cp_commit();
            cp_wait<1>();
        } else {
            cp_wait<0>();
        }
        __syncthreads();                 // Ks[buf] + Vt[buf] visible

        const float* ks_ = Ks[buf];
        const float* vt_ = Vt[buf];

        // S = Q . K^T : K fragments via ldmatrix
        float S[2][4][4] = {};
        #pragma unroll
        for (int ks = 0; ks < 8; ks++) {
            unsigned bf_[4][2];
            #pragma unroll
            for (int p = 0; p < 2; p++) {
                unsigned t[4];
                ldsm_x4(t, su32(&ks_[(p * 16 + brow) * KPAD + ks * 8 + bcol]));
                bf_[2 * p][0] = t[0]; bf_[2 * p][1] = t[1];
                bf_[2 * p + 1][0] = t[2]; bf_[2 * p + 1][1] = t[3];
            }
            #pragma unroll
            for (int nt = 0; nt < 4; nt++) {
                mma_tf32(S[0][nt], qa[0][ks][0], qa[0][ks][1], qa[0][ks][2], qa[0][ks][3],
                         bf_[nt][0], bf_[nt][1]);
                mma_tf32(S[1][nt], qa[1][ks][0], qa[1][ks][1], qa[1][ks][2], qa[1][ks][3],
                         bf_[nt][0], bf_[nt][1]);
            }
        }

        // linear softmax: P = exp(S)
        #pragma unroll
        for (int mt = 0; mt < 2; mt++) {
            #pragma unroll
            for (int nt = 0; nt < 4; nt++) {
                S[mt][nt][0] = __expf(S[mt][nt][0]);
                S[mt][nt][1] = __expf(S[mt][nt][1]);
                S[mt][nt][2] = __expf(S[mt][nt][2]);
                S[mt][nt][3] = __expf(S[mt][nt][3]);
                l[mt][0] += S[mt][nt][0] + S[mt][nt][1];
                l[mt][1] += S[mt][nt][2] + S[mt][nt][3];
            }
        }

        // O += P . V : P via shuffle transpose, V fragments via ldmatrix from Vt
        #pragma unroll
        for (int ks = 0; ks < 4; ks++) {
            const int srcA = qr * 4 + (qc >> 1);
            const int srcB = srcA + 2;
            const bool odd = qc & 1;
            unsigned amt[2][4];
            #pragma unroll
            for (int mt = 0; mt < 2; mt++) {
                float x0 = __shfl_sync(0xffffffffu, S[mt][ks][0], srcA);
                float x1 = __shfl_sync(0xffffffffu, S[mt][ks][1], srcA);
                float x2 = __shfl_sync(0xffffffffu, S[mt][ks][2], srcA);
                float x3 = __shfl_sync(0xffffffffu, S[mt][ks][3], srcA);
                float y0 = __shfl_sync(0xffffffffu, S[mt][ks][0], srcB);
                float y1 = __shfl_sync(0xffffffffu, S[mt][ks][1], srcB);
                float y2 = __shfl_sync(0xffffffffu, S[mt][ks][2], srcB);
                float y3 = __shfl_sync(0xffffffffu, S[mt][ks][3], srcB);
                amt[mt][0] = __float_as_uint(odd ? x1 : x0);
                amt[mt][1] = __float_as_uint(odd ? x3 : x2);
                amt[mt][2] = __float_as_uint(odd ? y1 : y0);
                amt[mt][3] = __float_as_uint(odd ? y3 : y2);
            }
            unsigned vf[8][2];
            #pragma unroll
            for (int p = 0; p < 4; p++) {
                unsigned t[4];
                ldsm_x4(t, su32(&vt_[(p * 16 + brow) * VTP + ks * 8 + bcol]));
                vf[2 * p][0] = t[0]; vf[2 * p][1] = t[1];
                vf[2 * p + 1][0] = t[2]; vf[2 * p + 1][1] = t[3];
            }
            #pragma unroll
            for (int nt = 0; nt < 8; nt++) {
                mma_tf32(O[0][nt], amt[0][0], amt[0][1], amt[0][2], amt[0][3],
                         vf[nt][0], vf[nt][1]);
                mma_tf32(O[1][nt], amt[1][0], amt[1][1], amt[1][2], amt[1][3],
                         vf[nt][0], vf[nt][1]);
            }
        }

        if (kt + 1 < NT) stsV(buf ^ 1);   // safe: everyone passed this iter's top sync
    }

    float* Xb = X + (size_t)b * SEQ * HID;
    #pragma unroll
    for (int mt = 0; mt < 2; mt++) {
        float l0 = l[mt][0], l1 = l[mt][1];
        #pragma unroll
        for (int off = 1; off < 4; off <<= 1) {
            l0 += __shfl_xor_sync(0xffffffffu, l0, off);
            l1 += __shfl_xor_sync(0xffffffffu, l1, off);
        }
        float inv0 = 1.f / l0, inv1 = 1.f / l1;

        int s0 = qt * 256 + w * 32 + mt * 16 + qr;
        int s1 = s0 + 8;
        int col0 = s0 & 1023, bit0 = s0 >> 10;
        int col1 = s1 & 1023, bit1 = s1 >> 10;
        #pragma unroll
        for (int nt = 0; nt < 8; nt++) {
            #pragma unroll
            for (int j = 0; j < 2; j++) {
                int d = nt * 8 + qc * 2 + j;
                Xb[(size_t)(h * 128 + 2 * d + bit0) * HID + col0] = O[mt][nt][j]     * inv0;
                Xb[(size_t)(h * 128 + 2 * d + bit1) * HID + col1] = O[mt][nt][2 + j] * inv1;
            }
        }
    }
}

// ================= row LayerNorm (vectorized) =================
__global__ __launch_bounds__(256)
void lnorm(const float* __restrict__ xin, const float* __restrict__ gw,
           const float* __restrict__ bw, float* __restrict__ yout) {
    __shared__ float rs[8], rs2[8];
    const int row = blockIdx.x;
    const float4* x4 = (const float4*)(xin + (size_t)row * HID);

    float4 v = x4[threadIdx.x];
    float s  = v.x + v.y + v.z + v.w;
    float s2 = v.x * v.x + v.y * v.y + v.z * v.z + v.w * v.w;
    #pragma unroll
    for (int off = 16; off; off >>= 1) {
        s  += __shfl_xor_sync(0xffffffffu, s,  off);
        s2 += __shfl_xor_sync(0xffffffffu, s2, off);
    }
    int wid = threadIdx.x >> 5, lane = threadIdx.x & 31;
    if (lane == 0) { rs[wid] = s; rs2[wid] = s2; }
    __syncthreads();
    float ts = 0.f, ts2 = 0.f;
    #pragma unroll
    for (int i = 0; i < 8; i++) { ts += rs[i]; ts2 += rs2[i]; }

    float mu  = ts * (1.f / HID);
    float var = ts2 * (1.f / HID) - mu * mu;
    float rstd = rsqrtf(var + 1e-5f);

    float4 g4 = ((const float4*)gw)[threadIdx.x];
    float4 b4 = ((const float4*)bw)[threadIdx.x];
    float4 y;
    y.x = (v.x - mu) * rstd * g4.x + b4.x;
    y.y = (v.y - mu) * rstd * g4.y + b4.y;
    y.z = (v.z - mu) * rstd * g4.z + b4.z;
    y.w = (v.w - mu) * rstd * g4.w + b4.w;
    ((float4*)(yout + (size_t)row * HID))[threadIdx.x] = y;
}

// ================= launch =================
extern "C" void kernel_launch(void* const* d_in, const int* in_sizes, int n_in,
                              void* d_out, int out_size) {
    const float* hidden = (const float*)d_in[0];
    const float* wq = (const float*)d_in[1];  const float* bq = (const float*)d_in[2];
    const float* wk = (const float*)d_in[3];  const float* bk = (const float*)d_in[4];
    const float* wv = (const float*)d_in[5];  const float* bv = (const float*)d_in[6];
    const float* wo = (const float*)d_in[7];  const float* bo = (const float*)d_in[8];
    const float* lng = (const float*)d_in[9]; const float* lnb = (const float*)d_in[10];
    const float* w1 = (const float*)d_in[11]; const float* b1 = (const float*)d_in[12];
    const float* w2 = (const float*)d_in[13]; const float* b2 = (const float*)d_in[14];
    const float* flng = (const float*)d_in[15]; const float* flnb = (const float*)d_in[16];
    float* out = (float*)d_out;

    float *q, *k, *v, *x, *t1, *o, *f1;
    cudaGetSymbolAddress((void**)&q,  g_q);
    cudaGetSymbolAddress((void**)&k,  g_k);
    cudaGetSymbolAddress((void**)&v,  g_v);
    cudaGetSymbolAddress((void**)&x,  g_x);
    cudaGetSymbolAddress((void**)&t1, g_t1);
    cudaGetSymbolAddress((void**)&o,  g_o);
    cudaGetSymbolAddress((void**)&f1, g_f1);

    // fused QKV projections
    qkv_gemm<<<dim3(12, TOK / 128), 128>>>(hidden, wq, bq, wk, bk, wv, bv, q, k, v);

    // fused GQA attention -> scrambled layout X
    flash5<<<dim3(SEQ / 256, 16, 2), 256>>>(q, k, v, x);

    // O-proj + residual, LN
    gemm128<1><<<dim3(HID / 128, TOK / 128), 128>>>(x, wo, bo, hidden, t1, HID, HID);
    lnorm<<<TOK, 256>>>(t1, lng, lnb, o);

    // FFN
    gemm128<2><<<dim3(HID / 128, TOK / 128), 128>>>(o, w1, b1, nullptr, f1, HID, HID);
    gemm128<1><<<dim3(HID / 128, TOK / 128), 128>>>(f1, w2, b2, o, t1, HID, HID);
    lnorm<<<TOK, 256>>>(t1, flng, flnb, out);
}

// round 11
// speedup vs baseline: 1.6238x; 1.6238x over previous
#include <cuda_runtime.h>
#include <cuda_fp16.h>
#include <cstdint>

#define TOK 4096
#define HID 1024
#define KVW 256
#define SEQ 2048

// fp32 scratch
__device__ float g_t1[TOK * HID];
__device__ float g_o [TOK * HID];
// fp16 scratch
__device__ __half g_hh [TOK * HID];
__device__ __half g_wqh[HID * HID];
__device__ __half g_wkh[KVW * HID];
__device__ __half g_wvh[KVW * HID];
__device__ __half g_woh[HID * HID];
__device__ __half g_w1h[HID * HID];
__device__ __half g_w2h[HID * HID];
__device__ __half g_qh [TOK * HID];
__device__ __half g_kh [TOK * KVW];
__device__ __half g_vh [TOK * KVW];
__device__ __half g_xh [TOK * HID];
__device__ __half g_oh [TOK * HID];
__device__ __half g_f1h[TOK * HID];

__device__ __forceinline__ unsigned su32(const void* p) {
    return (unsigned)__cvta_generic_to_shared(p);
}
__device__ __forceinline__ void cp16(unsigned s, const void* g) {
    asm volatile("cp.async.cg.shared.global [%0], [%1], 16;" :: "r"(s), "l"(g));
}
__device__ __forceinline__ void cp_commit() { asm volatile("cp.async.commit_group;"); }
template<int N> __device__ __forceinline__ void cp_wait() {
    asm volatile("cp.async.wait_group %0;" :: "n"(N));
}

// fp16 MMA: D(16x8,f32) += A(16x16,f16) * B(16x8,f16)
__device__ __forceinline__ void mma_f16(float c[4],
                                        unsigned a0, unsigned a1, unsigned a2, unsigned a3,
                                        unsigned b0, unsigned b1) {
    asm volatile(
        "mma.sync.aligned.m16n8k16.row.col.f32.f16.f16.f32 "
        "{%0,%1,%2,%3}, {%4,%5,%6,%7}, {%8,%9}, {%0,%1,%2,%3};"
        : "+f"(c[0]), "+f"(c[1]), "+f"(c[2]), "+f"(c[3])
        : "r"(a0), "r"(a1), "r"(a2), "r"(a3), "r"(b0), "r"(b1));
}

__device__ __forceinline__ void ldsm_x4(unsigned r[4], unsigned addr) {
    asm volatile("ldmatrix.sync.aligned.m8n8.x4.shared.b16 {%0,%1,%2,%3}, [%4];"
                 : "=r"(r[0]), "=r"(r[1]), "=r"(r[2]), "=r"(r[3]) : "r"(addr));
}
__device__ __forceinline__ void ldsm_x4_t(unsigned r[4], unsigned addr) {
    asm volatile("ldmatrix.sync.aligned.m8n8.x4.trans.shared.b16 {%0,%1,%2,%3}, [%4];"
                 : "=r"(r[0]), "=r"(r[1]), "=r"(r[2]), "=r"(r[3]) : "r"(addr));
}
// pack {lo, hi} floats -> f16x2 (lo in low half)
__device__ __forceinline__ unsigned pack2(float lo, float hi) {
    unsigned d;
    asm("cvt.rn.f16x2.f32 %0, %1, %2;" : "=r"(d) : "f"(hi), "f"(lo));
    return d;
}

// ================= fp32 -> fp16 conversion =================
__global__ __launch_bounds__(256)
void f2h(const float* __restrict__ in, __half* __restrict__ out, int n) {
    int i = (blockIdx.x * 256 + threadIdx.x) * 4;
    if (i < n) {
        float4 v = *(const float4*)(in + i);
        __half2 h0 = __floats2half2_rn(v.x, v.y);
        __half2 h1 = __floats2half2_rn(v.z, v.w);
        *(__half2*)(out + i)     = h0;
        *(__half2*)(out + i + 2) = h1;
    }
}

// ================= fp16 GEMM: 128x128 block, 4 warps x (64x64), BK=32 ============
// MODE 0: fp16 out, (acc+bias)*scale   MODE 1: fp32 out, +bias+res   MODE 2: fp16 out, relu(+bias)
#define GP 40   // smem pitch in halves (80B): phase-conflict-free for ldmatrix
template<int MODE>
__device__ __forceinline__ void gemm_body(
    const __half* __restrict__ A, const __half* __restrict__ Wb,
    const float* __restrict__ biasl, const float* __restrict__ res,
    void* Cv, int N, int ncol0, int K, int bm, float scale)
{
    __shared__ alignas(16) __half As[2][128 * GP];
    __shared__ alignas(16) __half Ws[2][128 * GP];

    const int tid = threadIdx.x, lane = tid & 31, w = tid >> 5;
    const int wm = w & 1, wn = w >> 1;
    const int qr = lane >> 2, qc = lane & 3;
    const int lrow = lane & 15, lcolh = (lane >> 4) << 3;   // ldmatrix addr pattern

    const __half* Ab = A + (size_t)bm * 128 * K;

    float acc[4][8][4] = {};
    const int NK = K / 32;

    auto stage = [&](int kt, int bf) {
        #pragma unroll
        for (int i = 0; i < 4; i++) {
            int idx = i * 128 + tid;            // 512 chunks: row = idx>>2, ch = idx&3
            int r = idx >> 2, ch = (idx & 3) * 8;
            cp16(su32(&As[bf][r * GP + ch]), Ab + (size_t)r * K + kt * 32 + ch);
            cp16(su32(&Ws[bf][r * GP + ch]), Wb + (size_t)r * K + kt * 32 + ch);
        }
    };

    stage(0, 0);
    cp_commit();

    for (int kt = 0; kt < NK; kt++) {
        const int buf = kt & 1;
        if (kt + 1 < NK) {
            stage(kt + 1, buf ^ 1);
            cp_commit();
            cp_wait<1>();
        } else {
            cp_wait<0>();
        }
        __syncthreads();

        const __half* as = As[buf];
        const __half* ws = Ws[buf];
        #pragma unroll
        for (int ks = 0; ks < 2; ks++) {        // two k16 steps per BK=32
            unsigned a[4][4], bfr[8][2];
            #pragma unroll
            for (int mt = 0; mt < 4; mt++)
                ldsm_x4(a[mt], su32(&as[(wm * 64 + mt * 16 + lrow) * GP + ks * 16 + lcolh]));
            #pragma unroll
            for (int p = 0; p < 4; p++) {
                unsigned t[4];
                ldsm_x4(t, su32(&ws[(wn * 64 + p * 16 + lrow) * GP + ks * 16 + lcolh]));
                bfr[2 * p][0] = t[0]; bfr[2 * p][1] = t[2];      // n-tile 2p:  k0-7, k8-15
                bfr[2 * p + 1][0] = t[1]; bfr[2 * p + 1][1] = t[3];
            }
            #pragma unroll
            for (int mt = 0; mt < 4; mt++)
                #pragma unroll
                for (int nt = 0; nt < 8; nt++)
                    mma_f16(acc[mt][nt], a[mt][0], a[mt][1], a[mt][2], a[mt][3],
                            bfr[nt][0], bfr[nt][1]);
        }
        __syncthreads();
    }

    #pragma unroll
    for (int mt = 0; mt < 4; mt++) {
        #pragma unroll
        for (int nt = 0; nt < 8; nt++) {
            int lcol = wn * 64 + nt * 8 + qc * 2;
            int col  = ncol0 + lcol;
            float b0 = biasl[lcol], b1 = biasl[lcol + 1];
            #pragma unroll
            for (int half = 0; half < 2; half++) {
                int row = bm * 128 + wm * 64 + mt * 16 + qr + half * 8;
                float v0 = acc[mt][nt][half * 2 + 0] + b0;
                float v1 = acc[mt][nt][half * 2 + 1] + b1;
                if (MODE == 1) {
                    v0 += res[(size_t)row * N + col];
                    v1 += res[(size_t)row * N + col + 1];
                    float2 o; o.x = v0; o.y = v1;
                    *(float2*)&((float*)Cv)[(size_t)row * N + col] = o;
                } else {
                    if (MODE == 0) { v0 *= scale; v1 *= scale; }
                    if (MODE == 2) { v0 = fmaxf(v0, 0.f); v1 = fmaxf(v1, 0.f); }
                    *(__half2*)&((__half*)Cv)[(size_t)row * N + col] =
                        __floats2half2_rn(v0, v1);
                }
            }
        }
    }
}

template<int MODE>
__global__ __launch_bounds__(128)
void gemm_h(const __half* __restrict__ A, const __half* __restrict__ W,
            const float* __restrict__ bias, const float* __restrict__ res,
            void* C, int N, int K) {
    int bn = blockIdx.x;
    gemm_body<MODE>(A, W + (size_t)bn * 128 * K, bias + bn * 128, res, C,
                    N, bn * 128, K, blockIdx.y, 1.0f);
}

__global__ __launch_bounds__(128)
void qkv_h(const __half* __restrict__ hidden,
           const __half* __restrict__ wq, const float* __restrict__ bq,
           const __half* __restrict__ wk, const float* __restrict__ bk,
           const __half* __restrict__ wv, const float* __restrict__ bv,
           __half* __restrict__ q, __half* __restrict__ k, __half* __restrict__ v) {
    int bn = blockIdx.x;
    const __half* W; const float* bias; __half* C; int N, nc; float sc = 1.0f;
    if (bn < 8)       { int j = bn;      W = wq + (size_t)j * 128 * HID; bias = bq + j * 128; C = q; N = HID; nc = j * 128; sc = 0.125f; }
    else if (bn < 10) { int j = bn - 8;  W = wk + (size_t)j * 128 * HID; bias = bk + j * 128; C = k; N = KVW; nc = j * 128; }
    else              { int j = bn - 10; W = wv + (size_t)j * 128 * HID; bias = bv + j * 128; C = v; N = KVW; nc = j * 128; }
    gemm_body<0>(hidden, W, bias, nullptr, C, N, nc, HID, blockIdx.y, sc);
}

// ================= flash attention fp16: 32 q-rows/warp, 32-key tiles =================
#define FP 72   // K/V smem pitch in halves (144B): conflict-free phases
__global__ __launch_bounds__(256)
void flash6(const __half* __restrict__ qh, const __half* __restrict__ kh,
            const __half* __restrict__ vh, __half* __restrict__ Xh) {
    __shared__ alignas(16) __half Ks[2][32 * FP];
    __shared__ alignas(16) __half Vs[2][32 * FP];

    const int b = blockIdx.z, h = blockIdx.y, qt = blockIdx.x, g = h >> 2;
    const int tid = threadIdx.x, lane = tid & 31, w = tid >> 5;
    const int qr = lane >> 2, qc = lane & 3;
    const int lrow = lane & 15, lcolh = (lane >> 4) << 3;

    // Q fragments (fp16, pre-scaled by 1/8 at QKV epilogue): 2 m-tiles x 4 k16 steps
    unsigned qa[2][4][4];
    #pragma unroll
    for (int mt = 0; mt < 2; mt++) {
        const __half2* q2 = (const __half2*)(qh +
            (size_t)(b * SEQ + qt * 256 + w * 32 + mt * 16) * HID + h * 64);
        #pragma unroll
        for (int ks = 0; ks < 4; ks++) {
            qa[mt][ks][0] = *(const unsigned*)&q2[(size_t)qr       * 512 + ks * 8 + qc];
            qa[mt][ks][1] = *(const unsigned*)&q2[(size_t)(qr + 8) * 512 + ks * 8 + qc];
            qa[mt][ks][2] = *(const unsigned*)&q2[(size_t)qr       * 512 + ks * 8 + qc + 4];
            qa[mt][ks][3] = *(const unsigned*)&q2[(size_t)(qr + 8) * 512 + ks * 8 + qc + 4];
        }
    }

    float l[2][2] = {};
    float O[2][8][4] = {};

    const __half* kb = kh + (size_t)b * SEQ * KVW + g * 64;
    const __half* vb = vh + (size_t)b * SEQ * KVW + g * 64;

    // staging: 32 rows x 128B per tensor; 256 chunks each; thread: 1 K + 1 V chunk
    const int r = tid >> 3;
    const int ch = (tid & 7) * 8;
    auto stage = [&](int kt, int bf) {
        cp16(su32(&Ks[bf][r * FP + ch]), kb + (size_t)(kt * 32 + r) * KVW + ch);
        cp16(su32(&Vs[bf][r * FP + ch]), vb + (size_t)(kt * 32 + r) * KVW + ch);
    };

    stage(0, 0);
    cp_commit();

    const int NT = SEQ / 32;
    for (int kt = 0; kt < NT; kt++) {
        const int buf = kt & 1;
        __syncthreads();
        if (kt + 1 < NT) {
            stage(kt + 1, buf ^ 1);
            cp_commit();
            cp_wait<1>();
        } else {
            cp_wait<0>();
        }
        __syncthreads();

        const __half* ks_ = Ks[buf];
        const __half* vs_ = Vs[buf];

        // S = Q . K^T : n = 32 keys (4 n-tiles), k = 64 d (4 k16 steps)
        float S[2][4][4] = {};
        #pragma unroll
        for (int ks = 0; ks < 4; ks++) {
            unsigned kf[4][2];
            #pragma unroll
            for (int p = 0; p < 2; p++) {
                unsigned t[4];
                ldsm_x4(t, su32(&ks_[(p * 16 + lrow) * FP + ks * 16 + lcolh]));
                kf[2 * p][0] = t[0]; kf[2 * p][1] = t[2];
                kf[2 * p + 1][0] = t[1]; kf[2 * p + 1][1] = t[3];
            }
            #pragma unroll
            for (int nt = 0; nt < 4; nt++) {
                mma_f16(S[0][nt], qa[0][ks][0], qa[0][ks][1], qa[0][ks][2], qa[0][ks][3],
                        kf[nt][0], kf[nt][1]);
                mma_f16(S[1][nt], qa[1][ks][0], qa[1][ks][1], qa[1][ks][2], qa[1][ks][3],
                        kf[nt][0], kf[nt][1]);
            }
        }

        // linear softmax: P = exp(S); lane-local row sums
        #pragma unroll
        for (int mt = 0; mt < 2; mt++) {
            #pragma unroll
            for (int nt = 0; nt < 4; nt++) {
                S[mt][nt][0] = __expf(S[mt][nt][0]);
                S[mt][nt][1] = __expf(S[mt][nt][1]);
                S[mt][nt][2] = __expf(S[mt][nt][2]);
                S[mt][nt][3] = __expf(S[mt][nt][3]);
                l[mt][0] += S[mt][nt][0] + S[mt][nt][1];
                l[mt][1] += S[mt][nt][2] + S[mt][nt][3];
            }
        }

        // O += P . V : P packs directly from S (C-frag == A-frag layout for fp16);
        // V fragments via ldmatrix.trans from [key][d] staging.
        #pragma unroll
        for (int ks2 = 0; ks2 < 2; ks2++) {     // k = 32 keys = 2 k16 steps
            unsigned amt[2][4];
            #pragma unroll
            for (int mt = 0; mt < 2; mt++) {
                amt[mt][0] = pack2(S[mt][2 * ks2][0],     S[mt][2 * ks2][1]);
                amt[mt][1] = pack2(S[mt][2 * ks2][2],     S[mt][2 * ks2][3]);
                amt[mt][2] = pack2(S[mt][2 * ks2 + 1][0], S[mt][2 * ks2 + 1][1]);
                amt[mt][3] = pack2(S[mt][2 * ks2 + 1][2], S[mt][2 * ks2 + 1][3]);
            }
            unsigned vf[8][2];
            #pragma unroll
            for (int p = 0; p < 4; p++) {       // n = 64 d = 8 n-tiles, 2 per x4.trans
                unsigned t[4];
                ldsm_x4_t(t, su32(&vs_[(ks2 * 16 + lrow) * FP + p * 16 + lcolh]));
                vf[2 * p][0] = t[0]; vf[2 * p][1] = t[1];        // keys0-7 / keys8-15
                vf[2 * p + 1][0] = t[2]; vf[2 * p + 1][1] = t[3];
            }
            #pragma unroll
            for (int nt = 0; nt < 8; nt++) {
                mma_f16(O[0][nt], amt[0][0], amt[0][1], amt[0][2], amt[0][3],
                        vf[nt][0], vf[nt][1]);
                mma_f16(O[1][nt], amt[1][0], amt[1][1], amt[1][2], amt[1][3],
                        vf[nt][0], vf[nt][1]);
            }
        }
    }

    // deferred row-sum reduction + normalize + bug-compatible scrambled fp16 store
    __half* Xb = Xh + (size_t)b * SEQ * HID;
    #pragma unroll
    for (int mt = 0; mt < 2; mt++) {
        float l0 = l[mt][0], l1 = l[mt][1];
        #pragma unroll
        for (int off = 1; off < 4; off <<= 1) {
            l0 += __shfl_xor_sync(0xffffffffu, l0, off);
            l1 += __shfl_xor_sync(0xffffffffu, l1, off);
        }
        float inv0 = 1.f / l0, inv1 = 1.f / l1;

        int s0 = qt * 256 + w * 32 + mt * 16 + qr;
        int s1 = s0 + 8;
        int col0 = s0 & 1023, bit0 = s0 >> 10;
        int col1 = s1 & 1023, bit1 = s1 >> 10;
        #pragma unroll
        for (int nt = 0; nt < 8; nt++) {
            #pragma unroll
            for (int j = 0; j < 2; j++) {
                int d = nt * 8 + qc * 2 + j;
                Xb[(size_t)(h * 128 + 2 * d + bit0) * HID + col0] = __float2half(O[mt][nt][j]     * inv0);
                Xb[(size_t)(h * 128 + 2 * d + bit1) * HID + col1] = __float2half(O[mt][nt][2 + j] * inv1);
            }
        }
    }
}

// ================= row LayerNorm (vectorized, optional fp16 secondary output) =========
template<int H16>
__global__ __launch_bounds__(256)
void lnorm(const float* __restrict__ xin, const float* __restrict__ gw,
           const float* __restrict__ bw, float* __restrict__ yout,
           __half* __restrict__ yh) {
    __shared__ float rs[8], rs2[8];
    const int row = blockIdx.x;
    const float4* x4 = (const float4*)(xin + (size_t)row * HID);

    float4 v = x4[threadIdx.x];
    float s  = v.x + v.y + v.z + v.w;
    float s2 = v.x * v.x + v.y * v.y + v.z * v.z + v.w * v.w;
    #pragma unroll
    for (int off = 16; off; off >>= 1) {
        s  += __shfl_xor_sync(0xffffffffu, s,  off);
        s2 += __shfl_xor_sync(0xffffffffu, s2, off);
    }
    int wid = threadIdx.x >> 5, lane = threadIdx.x & 31;
    if (lane == 0) { rs[wid] = s; rs2[wid] = s2; }
    __syncthreads();
    float ts = 0.f, ts2 = 0.f;
    #pragma unroll
    for (int i = 0; i < 8; i++) { ts += rs[i]; ts2 += rs2[i]; }

    float mu  = ts * (1.f / HID);
    float var = ts2 * (1.f / HID) - mu * mu;
    float rstd = rsqrtf(var + 1e-5f);

    float4 g4 = ((const float4*)gw)[threadIdx.x];
    float4 b4 = ((const float4*)bw)[threadIdx.x];
    float4 y;
    y.x = (v.x - mu) * rstd * g4.x + b4.x;
    y.y = (v.y - mu) * rstd * g4.y + b4.y;
    y.z = (v.z - mu) * rstd * g4.z + b4.z;
    y.w = (v.w - mu) * rstd * g4.w + b4.w;
    ((float4*)(yout + (size_t)row * HID))[threadIdx.x] = y;
    if (H16) {
        __half* yp = yh + (size_t)row * HID + threadIdx.x * 4;
        *(__half2*)yp       = __floats2half2_rn(y.x, y.y);
        *(__half2*)(yp + 2) = __floats2half2_rn(y.z, y.w);
    }
}

// ================= launch =================
extern "C" void kernel_launch(void* const* d_in, const int* in_sizes, int n_in,
                              void* d_out, int out_size) {
    const float* hidden = (const float*)d_in[0];
    const float* wq = (const float*)d_in[1];  const float* bq = (const float*)d_in[2];
    const float* wk = (const float*)d_in[3];  const float* bk = (const float*)d_in[4];
    const float* wv = (const float*)d_in[5];  const float* bv = (const float*)d_in[6];
    const float* wo = (const float*)d_in[7];  const float* bo = (const float*)d_in[8];
    const float* lng = (const float*)d_in[9]; const float* lnb = (const float*)d_in[10];
    const float* w1 = (const float*)d_in[11]; const float* b1 = (const float*)d_in[12];
    const float* w2 = (const float*)d_in[13]; const float* b2 = (const float*)d_in[14];
    const float* flng = (const float*)d_in[15]; const float* flnb = (const float*)d_in[16];
    float* out = (float*)d_out;

    float *t1, *o;
    __half *hh, *wqh, *wkh, *wvh, *woh, *w1h, *w2h, *qh, *kh, *vh, *xh, *oh, *f1h;
    cudaGetSymbolAddress((void**)&t1,  g_t1);
    cudaGetSymbolAddress((void**)&o,   g_o);
    cudaGetSymbolAddress((void**)&hh,  g_hh);
    cudaGetSymbolAddress((void**)&wqh, g_wqh);
    cudaGetSymbolAddress((void**)&wkh, g_wkh);
    cudaGetSymbolAddress((void**)&wvh, g_wvh);
    cudaGetSymbolAddress((void**)&woh, g_woh);
    cudaGetSymbolAddress((void**)&w1h, g_w1h);
    cudaGetSymbolAddress((void**)&w2h, g_w2h);
    cudaGetSymbolAddress((void**)&qh,  g_qh);
    cudaGetSymbolAddress((void**)&kh,  g_kh);
    cudaGetSymbolAddress((void**)&vh,  g_vh);
    cudaGetSymbolAddress((void**)&xh,  g_xh);
    cudaGetSymbolAddress((void**)&oh,  g_oh);
    cudaGetSymbolAddress((void**)&f1h, g_f1h);

    // fp32 -> fp16 prep
    f2h<<<TOK * HID / 1024, 256>>>(hidden, hh, TOK * HID);
    f2h<<<HID * HID / 1024, 256>>>(wq, wqh, HID * HID);
    f2h<<<KVW * HID / 1024, 256>>>(wk, wkh, KVW * HID);
    f2h<<<KVW * HID / 1024, 256>>>(wv, wvh, KVW * HID);
    f2h<<<HID * HID / 1024, 256>>>(wo, woh, HID * HID);
    f2h<<<HID * HID / 1024, 256>>>(w1, w1h, HID * HID);
    f2h<<<HID * HID / 1024, 256>>>(w2, w2h, HID * HID);

    // fused QKV projections (fp16 out; q pre-scaled by 1/8)
    qkv_h<<<dim3(12, TOK / 128), 128>>>(hh, wqh, bq, wkh, bk, wvh, bv, qh, kh, vh);

    // fused GQA attention -> scrambled fp16 X
    flash6<<<dim3(SEQ / 256, 16, 2), 256>>>(qh, kh, vh, xh);

    // O-proj + residual (fp32), LN -> o (fp32) + oh (fp16)
    gemm_h<1><<<dim3(HID / 128, TOK / 128), 128>>>(xh, woh, bo, hidden, t1, HID, HID);
    lnorm<1><<<TOK, 256>>>(t1, lng, lnb, o, oh);

    // FFN
    gemm_h<2><<<dim3(HID / 128, TOK / 128), 128>>>(oh, w1h, b1, nullptr, f1h, HID, HID);
    gemm_h<1><<<dim3(HID / 128, TOK / 128), 128>>>(f1h, w2h, b2, o, t1, HID, HID);
    lnorm<0><<<TOK, 256>>>(t1, flng, flnb, out, nullptr);
}

// round 12
// speedup vs baseline: 1.7586x; 1.0830x over previous
#include <cuda_runtime.h>
#include <cuda_fp16.h>
#include <cstdint>

#define TOK 4096
#define HID 1024
#define KVW 256
#define SEQ 2048

// fp32 scratch
__device__ float g_t1[TOK * HID];
__device__ float g_o [TOK * HID];
// fp16 scratch
__device__ __half g_hh [TOK * HID];
__device__ __half g_wqh[HID * HID];
__device__ __half g_wkh[KVW * HID];
__device__ __half g_wvh[KVW * HID];
__device__ __half g_woh[HID * HID];
__device__ __half g_w1h[HID * HID];
__device__ __half g_w2h[HID * HID];
__device__ __half g_qh [TOK * HID];
__device__ __half g_kh [TOK * KVW];
__device__ __half g_vh [TOK * KVW];
__device__ __half g_xh [TOK * HID];
__device__ __half g_oh [TOK * HID];
__device__ __half g_f1h[TOK * HID];

__device__ __forceinline__ unsigned su32(const void* p) {
    return (unsigned)__cvta_generic_to_shared(p);
}
__device__ __forceinline__ void cp16(unsigned s, const void* g) {
    asm volatile("cp.async.cg.shared.global [%0], [%1], 16;" :: "r"(s), "l"(g));
}
__device__ __forceinline__ void cp_commit() { asm volatile("cp.async.commit_group;"); }
template<int N> __device__ __forceinline__ void cp_wait() {
    asm volatile("cp.async.wait_group %0;" :: "n"(N));
}

__device__ __forceinline__ void mma_f16(float c[4],
                                        unsigned a0, unsigned a1, unsigned a2, unsigned a3,
                                        unsigned b0, unsigned b1) {
    asm volatile(
        "mma.sync.aligned.m16n8k16.row.col.f32.f16.f16.f32 "
        "{%0,%1,%2,%3}, {%4,%5,%6,%7}, {%8,%9}, {%0,%1,%2,%3};"
        : "+f"(c[0]), "+f"(c[1]), "+f"(c[2]), "+f"(c[3])
        : "r"(a0), "r"(a1), "r"(a2), "r"(a3), "r"(b0), "r"(b1));
}

__device__ __forceinline__ void ldsm_x4(unsigned r[4], unsigned addr) {
    asm volatile("ldmatrix.sync.aligned.m8n8.x4.shared.b16 {%0,%1,%2,%3}, [%4];"
                 : "=r"(r[0]), "=r"(r[1]), "=r"(r[2]), "=r"(r[3]) : "r"(addr));
}
__device__ __forceinline__ void ldsm_x4_t(unsigned r[4], unsigned addr) {
    asm volatile("ldmatrix.sync.aligned.m8n8.x4.trans.shared.b16 {%0,%1,%2,%3}, [%4];"
                 : "=r"(r[0]), "=r"(r[1]), "=r"(r[2]), "=r"(r[3]) : "r"(addr));
}
// pack {lo, hi} floats -> f16x2 (lo in low half)
__device__ __forceinline__ unsigned pack2(float lo, float hi) {
    unsigned d;
    asm("cvt.rn.f16x2.f32 %0, %1, %2;" : "=r"(d) : "f"(hi), "f"(lo));
    return d;
}
// 2^x elementwise on f16x2
__device__ __forceinline__ unsigned ex2h2(unsigned x) {
    unsigned d;
    asm("ex2.approx.f16x2 %0, %1;" : "=r"(d) : "r"(x));
    return d;
}

// ================= fused fp32 -> fp16 conversion (one launch, 7 segments) =============
__global__ __launch_bounds__(256)
void f2h_all(const float* __restrict__ hidden,
             const float* __restrict__ wq, const float* __restrict__ wk,
             const float* __restrict__ wv, const float* __restrict__ wo,
             const float* __restrict__ w1, const float* __restrict__ w2,
             __half* __restrict__ hh, __half* __restrict__ wqh,
             __half* __restrict__ wkh, __half* __restrict__ wvh,
             __half* __restrict__ woh, __half* __restrict__ w1h,
             __half* __restrict__ w2h) {
    int blk = blockIdx.x;               // each block converts 1024 elements
    const float* in; __half* out;
    if      (blk < 4096) { in = hidden; out = hh; }
    else if (blk < 5120) { in = wq; out = wqh; blk -= 4096; }
    else if (blk < 5376) { in = wk; out = wkh; blk -= 5120; }
    else if (blk < 5632) { in = wv; out = wvh; blk -= 5376; }
    else if (blk < 6656) { in = wo; out = woh; blk -= 5632; }
    else if (blk < 7680) { in = w1; out = w1h; blk -= 6656; }
    else                 { in = w2; out = w2h; blk -= 7680; }
    int i = blk * 1024 + threadIdx.x * 4;
    float4 v = *(const float4*)(in + i);
    *(__half2*)(out + i)     = __floats2half2_rn(v.x, v.y);
    *(__half2*)(out + i + 2) = __floats2half2_rn(v.z, v.w);
}

// ================= fp16 GEMM: 128x128 block, 4 warps x (64x64), BK=32 ============
#define GP 40
template<int MODE>
__device__ __forceinline__ void gemm_body(
    const __half* __restrict__ A, const __half* __restrict__ Wb,
    const float* __restrict__ biasl, const float* __restrict__ res,
    void* Cv, int N, int ncol0, int K, int bm, float scale)
{
    __shared__ alignas(16) __half As[2][128 * GP];
    __shared__ alignas(16) __half Ws[2][128 * GP];

    const int tid = threadIdx.x, lane = tid & 31, w = tid >> 5;
    const int wm = w & 1, wn = w >> 1;
    const int qr = lane >> 2, qc = lane & 3;
    const int lrow = lane & 15, lcolh = (lane >> 4) << 3;

    const __half* Ab = A + (size_t)bm * 128 * K;

    float acc[4][8][4] = {};
    const int NK = K / 32;

    auto stage = [&](int kt, int bf) {
        #pragma unroll
        for (int i = 0; i < 4; i++) {
            int idx = i * 128 + tid;
            int r = idx >> 2, ch = (idx & 3) * 8;
            cp16(su32(&As[bf][r * GP + ch]), Ab + (size_t)r * K + kt * 32 + ch);
            cp16(su32(&Ws[bf][r * GP + ch]), Wb + (size_t)r * K + kt * 32 + ch);
        }
    };

    stage(0, 0);
    cp_commit();

    for (int kt = 0; kt < NK; kt++) {
        const int buf = kt & 1;
        if (kt + 1 < NK) {
            stage(kt + 1, buf ^ 1);
            cp_commit();
            cp_wait<1>();
        } else {
            cp_wait<0>();
        }
        __syncthreads();

        const __half* as = As[buf];
        const __half* ws = Ws[buf];
        #pragma unroll
        for (int ks = 0; ks < 2; ks++) {
            unsigned a[4][4], bfr[8][2];
            #pragma unroll
            for (int mt = 0; mt < 4; mt++)
                ldsm_x4(a[mt], su32(&as[(wm * 64 + mt * 16 + lrow) * GP + ks * 16 + lcolh]));
            #pragma unroll
            for (int p = 0; p < 4; p++) {
                unsigned t[4];
                ldsm_x4(t, su32(&ws[(wn * 64 + p * 16 + lrow) * GP + ks * 16 + lcolh]));
                bfr[2 * p][0] = t[0]; bfr[2 * p][1] = t[2];
                bfr[2 * p + 1][0] = t[1]; bfr[2 * p + 1][1] = t[3];
            }
            #pragma unroll
            for (int mt = 0; mt < 4; mt++)
                #pragma unroll
                for (int nt = 0; nt < 8; nt++)
                    mma_f16(acc[mt][nt], a[mt][0], a[mt][1], a[mt][2], a[mt][3],
                            bfr[nt][0], bfr[nt][1]);
        }
        __syncthreads();
    }

    #pragma unroll
    for (int mt = 0; mt < 4; mt++) {
        #pragma unroll
        for (int nt = 0; nt < 8; nt++) {
            int lcol = wn * 64 + nt * 8 + qc * 2;
            int col  = ncol0 + lcol;
            float b0 = biasl[lcol], b1 = biasl[lcol + 1];
            #pragma unroll
            for (int half = 0; half < 2; half++) {
                int row = bm * 128 + wm * 64 + mt * 16 + qr + half * 8;
                float v0 = acc[mt][nt][half * 2 + 0] + b0;
                float v1 = acc[mt][nt][half * 2 + 1] + b1;
                if (MODE == 1) {
                    v0 += res[(size_t)row * N + col];
                    v1 += res[(size_t)row * N + col + 1];
                    float2 o; o.x = v0; o.y = v1;
                    *(float2*)&((float*)Cv)[(size_t)row * N + col] = o;
                } else {
                    if (MODE == 0) { v0 *= scale; v1 *= scale; }
                    if (MODE == 2) { v0 = fmaxf(v0, 0.f); v1 = fmaxf(v1, 0.f); }
                    *(__half2*)&((__half*)Cv)[(size_t)row * N + col] =
                        __floats2half2_rn(v0, v1);
                }
            }
        }
    }
}

template<int MODE>
__global__ __launch_bounds__(128)
void gemm_h(const __half* __restrict__ A, const __half* __restrict__ W,
            const float* __restrict__ bias, const float* __restrict__ res,
            void* C, int N, int K) {
    int bn = blockIdx.x;
    gemm_body<MODE>(A, W + (size_t)bn * 128 * K, bias + bn * 128, res, C,
                    N, bn * 128, K, blockIdx.y, 1.0f);
}

__global__ __launch_bounds__(128)
void qkv_h(const __half* __restrict__ hidden,
           const __half* __restrict__ wq, const float* __restrict__ bq,
           const __half* __restrict__ wk, const float* __restrict__ bk,
           const __half* __restrict__ wv, const float* __restrict__ bv,
           __half* __restrict__ q, __half* __restrict__ k, __half* __restrict__ v) {
    int bn = blockIdx.x;
    const __half* W; const float* bias; __half* C; int N, nc; float sc = 1.0f;
    // q pre-scaled by (1/8)*log2(e): flash computes P = 2^S directly
    if (bn < 8)       { int j = bn;      W = wq + (size_t)j * 128 * HID; bias = bq + j * 128; C = q; N = HID; nc = j * 128; sc = 0.125f * 1.44269504f; }
    else if (bn < 10) { int j = bn - 8;  W = wk + (size_t)j * 128 * HID; bias = bk + j * 128; C = k; N = KVW; nc = j * 128; }
    else              { int j = bn - 10; W = wv + (size_t)j * 128 * HID; bias = bv + j * 128; C = v; N = KVW; nc = j * 128; }
    gemm_body<0>(hidden, W, bias, nullptr, C, N, nc, HID, blockIdx.y, sc);
}

// ================= flash attention fp16: ex2.f16x2 softmax + ones-mma row sums ========
#define FP 72
#define ONESH2 0x3C003C00u
__global__ __launch_bounds__(256)
void flash7(const __half* __restrict__ qh, const __half* __restrict__ kh,
            const __half* __restrict__ vh, __half* __restrict__ Xh) {
    __shared__ alignas(16) __half Ks[2][32 * FP];
    __shared__ alignas(16) __half Vs[2][32 * FP];

    const int b = blockIdx.z, h = blockIdx.y, qt = blockIdx.x, g = h >> 2;
    const int tid = threadIdx.x, lane = tid & 31, w = tid >> 5;
    const int qr = lane >> 2, qc = lane & 3;
    const int lrow = lane & 15, lcolh = (lane >> 4) << 3;

    // Q fragments (fp16, pre-scaled by log2(e)/8): 2 m-tiles x 4 k16 steps
    unsigned qa[2][4][4];
    #pragma unroll
    for (int mt = 0; mt < 2; mt++) {
        const __half2* q2 = (const __half2*)(qh +
            (size_t)(b * SEQ + qt * 256 + w * 32 + mt * 16) * HID + h * 64);
        #pragma unroll
        for (int ks = 0; ks < 4; ks++) {
            qa[mt][ks][0] = *(const unsigned*)&q2[(size_t)qr       * 512 + ks * 8 + qc];
            qa[mt][ks][1] = *(const unsigned*)&q2[(size_t)(qr + 8) * 512 + ks * 8 + qc];
            qa[mt][ks][2] = *(const unsigned*)&q2[(size_t)qr       * 512 + ks * 8 + qc + 4];
            qa[mt][ks][3] = *(const unsigned*)&q2[(size_t)(qr + 8) * 512 + ks * 8 + qc + 4];
        }
    }

    float lacc[2][4] = {};          // ones-mma accumulators: c0 = rowsum(qr), c2 = rowsum(qr+8)
    float O[2][8][4] = {};

    const __half* kb = kh + (size_t)b * SEQ * KVW + g * 64;
    const __half* vb = vh + (size_t)b * SEQ * KVW + g * 64;

    const int r = tid >> 3;
    const int ch = (tid & 7) * 8;
    auto stage = [&](int kt, int bf) {
        cp16(su32(&Ks[bf][r * FP + ch]), kb + (size_t)(kt * 32 + r) * KVW + ch);
        cp16(su32(&Vs[bf][r * FP + ch]), vb + (size_t)(kt * 32 + r) * KVW + ch);
    };

    stage(0, 0);
    cp_commit();

    const int NT = SEQ / 32;
    for (int kt = 0; kt < NT; kt++) {
        const int buf = kt & 1;
        __syncthreads();
        if (kt + 1 < NT) {
            stage(kt + 1, buf ^ 1);
            cp_commit();
            cp_wait<1>();
        } else {
            cp_wait<0>();
        }
        __syncthreads();

        const __half* ks_ = Ks[buf];
        const __half* vs_ = Vs[buf];

        // S = Q . K^T  (S in log2 domain)
        float S[2][4][4] = {};
        #pragma unroll
        for (int ks = 0; ks < 4; ks++) {
            unsigned kf[4][2];
            #pragma unroll
            for (int p = 0; p < 2; p++) {
                unsigned t[4];
                ldsm_x4(t, su32(&ks_[(p * 16 + lrow) * FP + ks * 16 + lcolh]));
                kf[2 * p][0] = t[0]; kf[2 * p][1] = t[2];
                kf[2 * p + 1][0] = t[1]; kf[2 * p + 1][1] = t[3];
            }
            #pragma unroll
            for (int nt = 0; nt < 4; nt++) {
                mma_f16(S[0][nt], qa[0][ks][0], qa[0][ks][1], qa[0][ks][2], qa[0][ks][3],
                        kf[nt][0], kf[nt][1]);
                mma_f16(S[1][nt], qa[1][ks][0], qa[1][ks][1], qa[1][ks][2], qa[1][ks][3],
                        kf[nt][0], kf[nt][1]);
            }
        }

        // P = 2^S via ex2.approx.f16x2 -- outputs ARE the P.V A-fragments
        unsigned Pf[2][4][2];
        #pragma unroll
        for (int mt = 0; mt < 2; mt++) {
            #pragma unroll
            for (int nt = 0; nt < 4; nt++) {
                Pf[mt][nt][0] = ex2h2(pack2(S[mt][nt][0], S[mt][nt][1]));
                Pf[mt][nt][1] = ex2h2(pack2(S[mt][nt][2], S[mt][nt][3]));
            }
        }

        // O += P . V  and row sums via ones-B mma
        #pragma unroll
        for (int ks2 = 0; ks2 < 2; ks2++) {
            unsigned amt[2][4];
            #pragma unroll
            for (int mt = 0; mt < 2; mt++) {
                amt[mt][0] = Pf[mt][2 * ks2][0];
                amt[mt][1] = Pf[mt][2 * ks2][1];
                amt[mt][2] = Pf[mt][2 * ks2 + 1][0];
                amt[mt][3] = Pf[mt][2 * ks2 + 1][1];
            }
            mma_f16(lacc[0], amt[0][0], amt[0][1], amt[0][2], amt[0][3], ONESH2, ONESH2);
            mma_f16(lacc[1], amt[1][0], amt[1][1], amt[1][2], amt[1][3], ONESH2, ONESH2);

            unsigned vf[8][2];
            #pragma unroll
            for (int p = 0; p < 4; p++) {
                unsigned t[4];
                ldsm_x4_t(t, su32(&vs_[(ks2 * 16 + lrow) * FP + p * 16 + lcolh]));
                vf[2 * p][0] = t[0]; vf[2 * p][1] = t[1];
                vf[2 * p + 1][0] = t[2]; vf[2 * p + 1][1] = t[3];
            }
            #pragma unroll
            for (int nt = 0; nt < 8; nt++) {
                mma_f16(O[0][nt], amt[0][0], amt[0][1], amt[0][2], amt[0][3],
                        vf[nt][0], vf[nt][1]);
                mma_f16(O[1][nt], amt[1][0], amt[1][1], amt[1][2], amt[1][3],
                        vf[nt][0], vf[nt][1]);
            }
        }
    }

    // normalize + bug-compatible scrambled fp16 store (row sums direct from lacc)
    __half* Xb = Xh + (size_t)b * SEQ * HID;
    #pragma unroll
    for (int mt = 0; mt < 2; mt++) {
        float inv0 = 1.f / lacc[mt][0];
        float inv1 = 1.f / lacc[mt][2];

        int s0 = qt * 256 + w * 32 + mt * 16 + qr;
        int s1 = s0 + 8;
        int col0 = s0 & 1023, bit0 = s0 >> 10;
        int col1 = s1 & 1023, bit1 = s1 >> 10;
        #pragma unroll
        for (int nt = 0; nt < 8; nt++) {
            #pragma unroll
            for (int j = 0; j < 2; j++) {
                int d = nt * 8 + qc * 2 + j;
                Xb[(size_t)(h * 128 + 2 * d + bit0) * HID + col0] = __float2half(O[mt][nt][j]     * inv0);
                Xb[(size_t)(h * 128 + 2 * d + bit1) * HID + col1] = __float2half(O[mt][nt][2 + j] * inv1);
            }
        }
    }
}

// ================= row LayerNorm (vectorized, optional fp16 secondary output) =========
template<int H16>
__global__ __launch_bounds__(256)
void lnorm(const float* __restrict__ xin, const float* __restrict__ gw,
           const float* __restrict__ bw, float* __restrict__ yout,
           __half* __restrict__ yh) {
    __shared__ float rs[8], rs2[8];
    const int row = blockIdx.x;
    const float4* x4 = (const float4*)(xin + (size_t)row * HID);

    float4 v = x4[threadIdx.x];
    float s  = v.x + v.y + v.z + v.w;
    float s2 = v.x * v.x + v.y * v.y + v.z * v.z + v.w * v.w;
    #pragma unroll
    for (int off = 16; off; off >>= 1) {
        s  += __shfl_xor_sync(0xffffffffu, s,  off);
        s2 += __shfl_xor_sync(0xffffffffu, s2, off);
    }
    int wid = threadIdx.x >> 5, lane = threadIdx.x & 31;
    if (lane == 0) { rs[wid] = s; rs2[wid] = s2; }
    __syncthreads();
    float ts = 0.f, ts2 = 0.f;
    #pragma unroll
    for (int i = 0; i < 8; i++) { ts += rs[i]; ts2 += rs2[i]; }

    float mu  = ts * (1.f / HID);
    float var = ts2 * (1.f / HID) - mu * mu;
    float rstd = rsqrtf(var + 1e-5f);

    float4 g4 = ((const float4*)gw)[threadIdx.x];
    float4 b4 = ((const float4*)bw)[threadIdx.x];
    float4 y;
    y.x = (v.x - mu) * rstd * g4.x + b4.x;
    y.y = (v.y - mu) * rstd * g4.y + b4.y;
    y.z = (v.z - mu) * rstd * g4.z + b4.z;
    y.w = (v.w - mu) * rstd * g4.w + b4.w;
    ((float4*)(yout + (size_t)row * HID))[threadIdx.x] = y;
    if (H16) {
        __half* yp = yh + (size_t)row * HID + threadIdx.x * 4;
        *(__half2*)yp       = __floats2half2_rn(y.x, y.y);
        *(__half2*)(yp + 2) = __floats2half2_rn(y.z, y.w);
    }
}

// ================= launch =================
extern "C" void kernel_launch(void* const* d_in, const int* in_sizes, int n_in,
                              void* d_out, int out_size) {
    const float* hidden = (const float*)d_in[0];
    const float* wq = (const float*)d_in[1];  const float* bq = (const float*)d_in[2];
    const float* wk = (const float*)d_in[3];  const float* bk = (const float*)d_in[4];
    const float* wv = (const float*)d_in[5];  const float* bv = (const float*)d_in[6];
    const float* wo = (const float*)d_in[7];  const float* bo = (const float*)d_in[8];
    const float* lng = (const float*)d_in[9]; const float* lnb = (const float*)d_in[10];
    const float* w1 = (const float*)d_in[11]; const float* b1 = (const float*)d_in[12];
    const float* w2 = (const float*)d_in[13]; const float* b2 = (const float*)d_in[14];
    const float* flng = (const float*)d_in[15]; const float* flnb = (const float*)d_in[16];
    float* out = (float*)d_out;

    float *t1, *o;
    __half *hh, *wqh, *wkh, *wvh, *woh, *w1h, *w2h, *qh, *kh, *vh, *xh, *oh, *f1h;
    cudaGetSymbolAddress((void**)&t1,  g_t1);
    cudaGetSymbolAddress((void**)&o,   g_o);
    cudaGetSymbolAddress((void**)&hh,  g_hh);
    cudaGetSymbolAddress((void**)&wqh, g_wqh);
    cudaGetSymbolAddress((void**)&wkh, g_wkh);
    cudaGetSymbolAddress((void**)&wvh, g_wvh);
    cudaGetSymbolAddress((void**)&woh, g_woh);
    cudaGetSymbolAddress((void**)&w1h, g_w1h);
    cudaGetSymbolAddress((void**)&w2h, g_w2h);
    cudaGetSymbolAddress((void**)&qh,  g_qh);
    cudaGetSymbolAddress((void**)&kh,  g_kh);
    cudaGetSymbolAddress((void**)&vh,  g_vh);
    cudaGetSymbolAddress((void**)&xh,  g_xh);
    cudaGetSymbolAddress((void**)&oh,  g_oh);
    cudaGetSymbolAddress((void**)&f1h, g_f1h);

    // fp32 -> fp16 prep (single fused launch)
    f2h_all<<<8704, 256>>>(hidden, wq, wk, wv, wo, w1, w2,
                           hh, wqh, wkh, wvh, woh, w1h, w2h);

    // fused QKV projections (fp16 out; q pre-scaled by log2(e)/8)
    qkv_h<<<dim3(12, TOK / 128), 128>>>(hh, wqh, bq, wkh, bk, wvh, bv, qh, kh, vh);

    // fused GQA attention -> scrambled fp16 X
    flash7<<<dim3(SEQ / 256, 16, 2), 256>>>(qh, kh, vh, xh);

    // O-proj + residual (fp32), LN -> o (fp32) + oh (fp16)
    gemm_h<1><<<dim3(HID / 128, TOK / 128), 128>>>(xh, woh, bo, hidden, t1, HID, HID);
    lnorm<1><<<TOK, 256>>>(t1, lng, lnb, o, oh);

    // FFN
    gemm_h<2><<<dim3(HID / 128, TOK / 128), 128>>>(oh, w1h, b1, nullptr, f1h, HID, HID);
    gemm_h<1><<<dim3(HID / 128, TOK / 128), 128>>>(f1h, w2h, b2, o, t1, HID, HID);
    lnorm<0><<<TOK, 256>>>(t1, flng, flnb, out, nullptr);
}